// round 4
// baseline (speedup 1.0000x reference)
#include <cuda_runtime.h>

#define HN 50
#define GN 200
#define TN 512
#define BN 2048

__device__ __forceinline__ unsigned long long pack2(float x, float y) {
    unsigned long long r;
    asm("mov.b64 %0, {%1, %2};" : "=l"(r) : "f"(x), "f"(y));
    return r;
}

__device__ __forceinline__ void unpack2(unsigned long long v, float &x, float &y) {
    asm("mov.b64 {%0, %1}, %2;" : "=f"(x), "=f"(y) : "l"(v));
}

// Packed dual-fp32 FMA (Blackwell FFMA2) — 2x fp32 FMA throughput vs scalar FFMA.
__device__ __forceinline__ unsigned long long fma2(unsigned long long a,
                                                   unsigned long long b,
                                                   unsigned long long c) {
    unsigned long long r;
    asm("fma.rn.f32x2 %0, %1, %2, %3;" : "=l"(r) : "l"(a), "l"(b), "l"(c));
    return r;
}

__device__ __forceinline__ float sigmoid_f(float x) {
    // exp-based: ~1e-7 rel err, safe for 512-step recurrence
    return __fdividef(1.0f, 1.0f + __expf(-x));
}

__device__ __forceinline__ float tanh_f(float x) {
    float e = __expf(-2.0f * fabsf(x));          // e in (0,1], no overflow
    float t = __fdividef(1.0f - e, 1.0f + e);
    return copysignf(t, x);
}

__global__ void __launch_bounds__(256, 3)
lstm_kernel(const float* __restrict__ x,     // [B, T, 1]
            const float* __restrict__ W_ih,  // [4H, 1]
            const float* __restrict__ W_hh,  // [4H, H]
            const float* __restrict__ b_ih,  // [4H]
            const float* __restrict__ b_hh,  // [4H]
            const float* __restrict__ W_lin, // [1, H]
            const float* __restrict__ b_lin, // [1]
            float* __restrict__ out)         // [B, 1]
{
    __shared__ __align__(16) float hsm[56];  // h, zero-padded to 52+ floats
    __shared__ float acts[GN];
    __shared__ float xs[TN];

    const int b   = blockIdx.x;
    const int tid = threadIdx.x;

    // Preload this sequence's x into SMEM (2 KB).
    for (int t = tid; t < TN; t += 256) xs[t] = x[b * TN + t];

    // Per-thread gate row of W_hh packed into f32x2 registers.
    unsigned long long w[26];
    float bias = 0.0f, wih = 0.0f;
    if (tid < GN) {
        const float2* wr = (const float2*)(W_hh + tid * HN);  // 8B-aligned (50*4*g)
        #pragma unroll
        for (int j = 0; j < 25; j++) {
            float2 f = wr[j];
            w[j] = pack2(f.x, f.y);
        }
        w[25] = 0ull;                     // pads h[50], h[51]
        bias  = b_ih[tid] + b_hh[tid];
        wih   = W_ih[tid];
    } else {
        #pragma unroll
        for (int j = 0; j < 26; j++) w[j] = 0ull;
    }

    if (tid < 56) hsm[tid] = 0.0f;        // h0 = 0 (+ padding stays 0 forever)
    float c = 0.0f;                        // c state lives in threads [0,50)

    // gate kind: i[0,50) f[50,100) sigmoid; g[100,150) tanh; o[150,200) sigmoid
    const bool is_tanh_gate = (tid >= 100 && tid < 150);

    __syncthreads();

    for (int t = 0; t < TN; t++) {
        // ---- phase 1: gate pre-activations + nonlinearity (200 threads) ----
        if (tid < GN) {
            const ulonglong2* h2 = (const ulonglong2*)hsm;
            unsigned long long a0 = 0ull, a1 = 0ull;
            #pragma unroll
            for (int j = 0; j < 13; j++) {
                ulonglong2 v = h2[j];                 // LDS.128 broadcast
                a0 = fma2(w[2 * j],     v.x, a0);
                a1 = fma2(w[2 * j + 1], v.y, a1);
            }
            float s0x, s0y, s1x, s1y;
            unpack2(a0, s0x, s0y);
            unpack2(a1, s1x, s1y);
            float pre = fmaf(xs[t], wih, bias) + ((s0x + s0y) + (s1x + s1y));
            acts[tid] = is_tanh_gate ? tanh_f(pre) : sigmoid_f(pre);
        }
        __syncthreads();

        // ---- phase 2: state update (50 threads) ----
        if (tid < HN) {
            float i_ = acts[tid];
            float f_ = acts[tid + HN];
            float g_ = acts[tid + 2 * HN];
            float o_ = acts[tid + 3 * HN];
            c = fmaf(f_, c, i_ * g_);
            hsm[tid] = o_ * tanh_f(c);
        }
        __syncthreads();
    }

    // ---- final linear head: out[b] = h . W_lin + b_lin (once, cheap) ----
    if (tid == 0) {
        float s = b_lin[0];
        #pragma unroll
        for (int j = 0; j < HN; j++) s = fmaf(hsm[j], W_lin[j], s);
        out[b] = s;
    }
}

extern "C" void kernel_launch(void* const* d_in, const int* in_sizes, int n_in,
                              void* d_out, int out_size) {
    const float* x     = (const float*)d_in[0];
    const float* W_ih  = (const float*)d_in[1];
    const float* W_hh  = (const float*)d_in[2];
    const float* b_ih  = (const float*)d_in[3];
    const float* b_hh  = (const float*)d_in[4];
    const float* W_lin = (const float*)d_in[5];
    const float* b_lin = (const float*)d_in[6];
    float* out = (float*)d_out;

    lstm_kernel<<<BN, 256>>>(x, W_ih, W_hh, b_ih, b_hh, W_lin, b_lin, out);
}

// round 5
// speedup vs baseline: 1.2874x; 1.2874x over previous
#include <cuda_runtime.h>

#define HN 50
#define TN 512
#define BN 2048

typedef unsigned long long u64;

__device__ __forceinline__ u64 pack2(float x, float y) {
    u64 r; asm("mov.b64 %0, {%1, %2};" : "=l"(r) : "f"(x), "f"(y)); return r;
}
__device__ __forceinline__ void unpack2(u64 v, float &x, float &y) {
    asm("mov.b64 {%0, %1}, %2;" : "=f"(x), "=f"(y) : "l"(v));
}
// Packed dual-fp32 FMA (Blackwell FFMA2): 2 MACs per issue.
__device__ __forceinline__ u64 fma2(u64 a, u64 b, u64 c) {
    u64 r; asm("fma.rn.f32x2 %0, %1, %2, %3;" : "=l"(r) : "l"(a), "l"(b), "l"(c)); return r;
}

// Same numerics as the passing R4 kernel (rel_err 3.8e-7): MUL+EX2+ADD+RCP.
// Saturates cleanly at +/-inf (exp->inf => rcp->0), no NaN.
__device__ __forceinline__ float sigmoid_f(float x) {
    float e = __expf(-x);
    return __fdividef(1.0f, 1.0f + e);
}

__global__ void __launch_bounds__(128, 4)
lstm_kernel(const float* __restrict__ x,     // [B, T, 1]
            const float* __restrict__ W_ih,  // [4H, 1]
            const float* __restrict__ W_hh,  // [4H, H]
            const float* __restrict__ b_ih,  // [4H]
            const float* __restrict__ b_hh,  // [4H]
            const float* __restrict__ W_lin, // [1, H]
            const float* __restrict__ b_lin, // [1]
            float* __restrict__ out)         // [B, 1]
{
    __shared__ __align__(16) float hbuf[2][64]; // double-buffered h (50 used)
    __shared__ float xs[TN];

    const int b    = blockIdx.x;
    const int tid  = threadIdx.x;
    const int lane = tid & 31;
    const int w    = tid >> 5;
    const int p    = (w << 4) | (lane & 15);   // pair (h-index), 0..63; valid < 50
    const int role = (lane >> 4);              // 0 = IG lane, 1 = FO lane
    const bool valid = (p < HN);
    const int  pc    = valid ? p : (HN - 1);   // clamp for safe weight loads

    // Preload x sequence (coalesced).
    for (int t = tid; t < TN; t += 128) xs[t] = x[b * TN + t];

    // Zero both h buffers.
    if (tid < 128) ((float*)hbuf)[tid] = 0.0f;

    // Gate rows (PyTorch order i,f,g,o): rowA = i|f, rowB = g|o.
    const int rowA = pc + role * HN;           // i (role 0) or f (role 1)
    const int rowB = rowA + 2 * HN;            // g (role 0) or o (role 1)

    // Pack 2 x 50 weights into f32x2 registers (rows are 8B-aligned: 200B stride).
    u64 wA[25], wB[25];
    {
        const float2* ra = (const float2*)(W_hh + rowA * HN);
        const float2* rb = (const float2*)(W_hh + rowB * HN);
        #pragma unroll
        for (int j = 0; j < 25; j++) {
            float2 fa = ra[j], fb = rb[j];
            wA[j] = pack2(fa.x, fa.y);
            wB[j] = pack2(fb.x, fb.y);
        }
    }
    const float biasA = b_ih[rowA] + b_hh[rowA];
    const float biasB = b_ih[rowB] + b_hh[rowB];
    const float wihA  = W_ih[rowA];
    const float wihB  = W_ih[rowB];
    // preB activation: IG lane needs tanh(preB) = 2*sigmoid(2*preB)-1; FO lane sigmoid(preB).
    const float scaleB = role ? 1.0f : 2.0f;

    float c = 0.0f;                            // cell state, lives in FO lanes

    __syncthreads();

#define LSTM_STEP(HR, HW, T)                                                   \
    {                                                                          \
        const float*      hr = &hbuf[HR][0];                                   \
        const ulonglong2* h2 = (const ulonglong2*)hr;                          \
        u64 a0 = 0ull, a1 = 0ull, d0 = 0ull, d1 = 0ull;                        \
        _Pragma("unroll")                                                      \
        for (int k = 0; k < 12; k++) {                                         \
            ulonglong2 v = h2[k];            /* LDS.128 broadcast */           \
            a0 = fma2(wA[2 * k],     v.x, a0);                                 \
            a1 = fma2(wA[2 * k + 1], v.y, a1);                                 \
            d0 = fma2(wB[2 * k],     v.x, d0);                                 \
            d1 = fma2(wB[2 * k + 1], v.y, d1);                                 \
        }                                                                      \
        u64 vt = *(const u64*)(hr + 48);     /* h[48],h[49] */                 \
        a0 = fma2(wA[24], vt, a0);                                             \
        d0 = fma2(wB[24], vt, d0);                                             \
        float ax, ay, az, aw, dx, dy, dz, dw;                                  \
        unpack2(a0, ax, ay); unpack2(a1, az, aw);                              \
        unpack2(d0, dx, dy); unpack2(d1, dz, dw);                              \
        float xt = xs[T];                                                      \
        float preA = ((ax + ay) + (az + aw)) + fmaf(xt, wihA, biasA);          \
        float preB = ((dx + dy) + (dz + dw)) + fmaf(xt, wihB, biasB);          \
        float sA = sigmoid_f(preA);          /* i (IG) or f (FO) */            \
        float sB = sigmoid_f(preB * scaleB); /* sig(2g)->tanh | o  */          \
        float val = fmaf(2.0f * sA, sB, -sA); /* IG: i*g = sA*(2sB-1) */       \
        float got = __shfl_xor_sync(0xFFFFFFFFu, val, 16);                     \
        if (role && valid) {                                                   \
            c = fmaf(sA, c, got);            /* c = f*c + i*g */               \
            float tc = fmaf(2.0f, sigmoid_f(2.0f * c), -1.0f); /* tanh(c) */   \
            hbuf[HW][p] = sB * tc;           /* h = o*tanh(c) */               \
        }                                                                      \
        __syncthreads();                                                       \
    }

    for (int t = 0; t < TN; t += 2) {
        LSTM_STEP(0, 1, t)
        LSTM_STEP(1, 0, t + 1)
    }
#undef LSTM_STEP

    // Final head: out[b] = h . W_lin + b_lin  (final h is in hbuf[0])
    if (tid == 0) {
        float s = b_lin[0];
        #pragma unroll
        for (int j = 0; j < HN; j++) s = fmaf(hbuf[0][j], W_lin[j], s);
        out[b] = s;
    }
}

extern "C" void kernel_launch(void* const* d_in, const int* in_sizes, int n_in,
                              void* d_out, int out_size) {
    const float* x     = (const float*)d_in[0];
    const float* W_ih  = (const float*)d_in[1];
    const float* W_hh  = (const float*)d_in[2];
    const float* b_ih  = (const float*)d_in[3];
    const float* b_hh  = (const float*)d_in[4];
    const float* W_lin = (const float*)d_in[5];
    const float* b_lin = (const float*)d_in[6];
    float* out = (float*)d_out;

    lstm_kernel<<<BN, 128>>>(x, W_ih, W_hh, b_ih, b_hh, W_lin, b_lin, out);
}